// round 15
// baseline (speedup 1.0000x reference)
#include <cuda_runtime.h>
#include <cuda_fp16.h>
#include <cstdint>

#define LN_EPS 1e-5f

// ============================ PTX helpers ============================
__device__ __forceinline__ uint32_t smem_u32(const void* p) {
    uint32_t a;
    asm("{ .reg .u64 t; cvta.to.shared.u64 t, %1; cvt.u32.u64 %0, t; }"
        : "=r"(a) : "l"(p));
    return a;
}

__device__ __forceinline__ uint32_t swz64(uint32_t off) {
    return off ^ ((off >> 3) & 0x30);
}

#define LDSM4(r, addr)                                                        \
    asm volatile(                                                             \
        "ldmatrix.sync.aligned.m8n8.x4.shared.b16 {%0,%1,%2,%3}, [%4];"       \
        : "=r"((r)[0]), "=r"((r)[1]), "=r"((r)[2]), "=r"((r)[3])              \
        : "r"(addr))

// f32-accumulate fp16 MMA (main product)
#define MMAF16(d, a, b0, b1)                                                  \
    asm volatile(                                                             \
        "mma.sync.aligned.m16n8k16.row.col.f32.f16.f16.f32 "                  \
        "{%0,%1,%2,%3}, {%4,%5,%6,%7}, {%8,%9}, {%0,%1,%2,%3};"               \
        : "+f"((d)[0]), "+f"((d)[1]), "+f"((d)[2]), "+f"((d)[3])              \
        : "r"((a)[0]), "r"((a)[1]), "r"((a)[2]), "r"((a)[3]),                 \
          "r"(b0), "r"(b1))

// f16-accumulate fp16 MMA (correction products; C/D = 2x f16x2 regs)
#define MMAF16H(d, a, b0, b1)                                                 \
    asm volatile(                                                             \
        "mma.sync.aligned.m16n8k16.row.col.f16.f16.f16.f16 "                  \
        "{%0,%1}, {%2,%3,%4,%5}, {%6,%7}, {%0,%1};"                           \
        : "+r"((d)[0]), "+r"((d)[1])                                          \
        : "r"((a)[0]), "r"((a)[1]), "r"((a)[2]), "r"((a)[3]),                 \
          "r"(b0), "r"(b1))

#define CP_ASYNC16(dst, src)                                                  \
    asm volatile("cp.async.cg.shared.global [%0], [%1], 16;"                  \
                 :: "r"(dst), "l"(src))
#define CP_ASYNC_COMMIT() asm volatile("cp.async.commit_group;" ::: "memory")
#define CP_ASYNC_WAIT1()  asm volatile("cp.async.wait_group 1;" ::: "memory")
#define CP_ASYNC_WAIT0()  asm volatile("cp.async.wait_group 0;" ::: "memory")

// ============================ geometry ============================
constexpr int TM    = 128;
constexpr int KCH   = 32;                 // 64 B rows (fp16)
constexpr int ATILE = TM * KCH * 2;       // 8192 B per A limb tile

__host__ __device__ constexpr int npass_of(int dout) {
    return dout > 128 ? 128 : dout;
}
__host__ __device__ constexpr int bufb_of(int dout) {
    return 2 * ATILE + 2 * npass_of(dout) * KCH * 2;
}
__host__ __device__ constexpr int smem_of(int dout) {
    return 2 * bufb_of(dout) + 7168;
}

// ============================ scratch ============================
__device__ __align__(256) float  g_h[98304ull * 512];
__device__ __align__(256) __half g_a0[98304ull * 768];
__device__ __align__(256) __half g_a1[98304ull * 768];
__device__ __align__(256) __half g_c0[98304ull * 512];
__device__ __align__(256) __half g_c1[98304ull * 512];
__device__ __align__(256) __half g_p0[98304ull * 128];
__device__ __align__(256) __half g_p1[98304ull * 128];
__device__ __align__(256) __half g_w0[724992];
__device__ __align__(256) __half g_w1[724992];
__device__ float g_psum[64 * 32];
__device__ float g_pcnt[64];

// ============================ 2-way fp16 split ============================
__device__ __forceinline__ void split2(float a, __half& h0, __half& h1) {
    h0 = __float2half_rn(a);
    h1 = __float2half_rn(a - __half2float(h0));
}
__device__ __forceinline__ uint32_t pack2(__half a, __half b) {
    return ((uint32_t)__half_as_ushort(b) << 16) | (uint32_t)__half_as_ushort(a);
}

// ============================ W prep ============================
__global__ void split_w_all(const float* __restrict__ W1,
                            const float* __restrict__ W2,
                            const float* __restrict__ W3,
                            const float* __restrict__ W4) {
    int i = blockIdx.x * 256 + threadIdx.x;
    if (i >= 724992) return;
    float v;
    if (i < 393216) v = W1[i];
    else if (i < 655360) v = W2[i - 393216];
    else if (i < 720896) v = W3[i - 655360];
    else v = W4[i - 720896];
    __half h0, h1;
    split2(v, h0, h1);
    g_w0[i] = h0;
    g_w1[i] = h1;
}

// ============================ input convert ============================
__global__ __launch_bounds__(256) void convert_in(
    const float* __restrict__ x, __half* __restrict__ o0,
    __half* __restrict__ o1, int total8) {
    int i = blockIdx.x * 256 + threadIdx.x;
    if (i >= total8) return;
    int r = i / 96;
    int q = i - r * 96;
    const float* src = x + (int64_t)r * 768 + q * 8;
    float4 v0 = *(const float4*)src;
    float4 v1 = *(const float4*)(src + 4);
    float xx[8] = {v0.x, v0.y, v0.z, v0.w, v1.x, v1.y, v1.z, v1.w};
    __half h0[8], h1[8];
#pragma unroll
    for (int j = 0; j < 8; j++) split2(xx[j], h0[j], h1[j]);
    int64_t o = (int64_t)r * 768 + q * 8;
    *(uint4*)(o0 + o) = make_uint4(pack2(h0[0], h0[1]), pack2(h0[2], h0[3]),
                                   pack2(h0[4], h0[5]), pack2(h0[6], h0[7]));
    *(uint4*)(o1 + o) = make_uint4(pack2(h1[0], h1[1]), pack2(h1[2], h1[3]),
                                   pack2(h1[4], h1[5]), pack2(h1[6], h1[7]));
}

// ============================ chunk prefetch ============================
template <int DIN, int NPASS>
__device__ __forceinline__ void issue_chunk(
    uint32_t smb, int buf, int64_t r0, int n0, int k0,
    const __half* __restrict__ a0, const __half* __restrict__ a1,
    const __half* w0, const __half* w1, int tid) {
    constexpr int BUFB  = 2 * ATILE + 2 * NPASS * 64;
    constexpr int WTILE = NPASS * 64;
    const uint32_t base = smb + buf * BUFB;
    const __half* ap[2] = {a0, a1};
    const __half* wp[2] = {w0, w1};
#pragma unroll
    for (int s = 0; s < 2; s++) {
#pragma unroll
        for (int it = 0; it < 2; it++) {
            int i = tid + it * 256;
            int r = i >> 2, q = i & 3;
            const void* src = ap[s] + (r0 + r) * (int64_t)DIN + k0 + q * 8;
            uint32_t dst = base + s * ATILE + swz64((uint32_t)(r * 64 + q * 16));
            CP_ASYNC16(dst, src);
        }
    }
#pragma unroll
    for (int t = 0; t < 2; t++) {
        for (int i = tid; i < NPASS * 4; i += 256) {
            int r = i >> 2, q = i & 3;
            const void* src = wp[t] + (n0 + r) * (int64_t)DIN + k0 + q * 8;
            uint32_t dst = base + 2 * ATILE + t * WTILE +
                           swz64((uint32_t)(r * 64 + q * 16));
            CP_ASYNC16(dst, src);
        }
    }
}

// ============================ layer kernel ============================
// OMODE 0: fp32 h out + LN stats + fused phase-2 LN/ReLU/split -> planes
// OMODE 1: fused LN/ReLU/split from regs (NT==1), no fp32 out
// OMODE 2: fp32 out only
template <int DIN, int DOUT, int OMODE>
__global__ __launch_bounds__(256, 2) void layer_kernel(
    const __half* __restrict__ a0, const __half* __restrict__ a1, int w_off,
    const float* __restrict__ bias,
    const float* __restrict__ go, const float* __restrict__ bo,
    float* __restrict__ outf,
    __half* __restrict__ o0, __half* __restrict__ o1) {
    extern __shared__ char sm[];
    const uint32_t smb = smem_u32(sm);
    const int tid  = threadIdx.x;
    const int lane = tid & 31;
    const int wid  = tid >> 5;
    const int64_t r0 = (int64_t)blockIdx.x * TM;

    constexpr int NPASS = npass_of(DOUT);
    constexpr int NT    = DOUT / NPASS;
    constexpr int WC    = NPASS / 2;
    constexpr int NFRAG = WC / 8;
    constexpr int NCH   = DIN / KCH;
    constexpr int BUFB  = 2 * ATILE + 2 * NPASS * 64;
    constexpr int WTILE = NPASS * 64;
    constexpr int SM_P  = 2 * BUFB;
    static_assert(OMODE != 1 || NT == 1, "fused reg split needs NT==1");
    static_assert(NFRAG >= 2, "need at least 2 fragments per warp");

    const int wr  = wid >> 1;
    const int wc  = wid & 1;
    const int R0  = wr * 32;
    const int C0w = wc * WC;

    const int sub  = lane >> 3;
    const int arow = (sub & 1) * 8 + (lane & 7);
    const int acol = (sub >> 1) * 8;
    const int brow = (sub >> 1) * 8 + (lane & 7);
    const int bcol = (sub & 1) * 8;

    float* bias_s = (float*)(sm + SM_P);
    float* go_s   = (float*)(sm + SM_P + 2048);
    float* bo_s   = (float*)(sm + SM_P + 4096);
    float* s1_s   = (float*)(sm + SM_P + 6144);
    float* s2_s   = (float*)(sm + SM_P + 6656);

    for (int i = tid; i < DOUT; i += 256) bias_s[i] = bias[i];
    if (OMODE != 2)
        for (int i = tid; i < DOUT; i += 256) {
            go_s[i] = go[i];
            bo_s[i] = bo[i];
        }
    if (OMODE != 2 && tid < TM) {
        s1_s[tid] = 0.f;
        s2_s[tid] = 0.f;
    }
    __syncthreads();

    const __half* w0 = g_w0 + w_off;
    const __half* w1 = g_w1 + w_off;

    float    acc[2][NFRAG][4];     // main product (f32 accum)
    uint32_t cac[2][NFRAG][2];     // corrections  (f16 accum, 2x f16x2)

    for (int nt = 0; nt < NT; nt++) {
#pragma unroll
        for (int i = 0; i < 2; i++)
#pragma unroll
            for (int j = 0; j < NFRAG; j++) {
#pragma unroll
                for (int q = 0; q < 4; q++) acc[i][j][q] = 0.f;
                cac[i][j][0] = 0u;
                cac[i][j][1] = 0u;
            }

        const int n0 = nt * NPASS;
        issue_chunk<DIN, NPASS>(smb, 0, r0, n0, 0, a0, a1, w0, w1, tid);
        CP_ASYNC_COMMIT();

        for (int ch = 0; ch < NCH; ch++) {
            if (ch + 1 < NCH) {
                issue_chunk<DIN, NPASS>(smb, (ch + 1) & 1, r0, n0,
                                        (ch + 1) * KCH, a0, a1, w0, w1, tid);
                CP_ASYNC_COMMIT();
                CP_ASYNC_WAIT1();
            } else {
                CP_ASYNC_WAIT0();
            }
            __syncthreads();

            const uint32_t base = smb + (ch & 1) * BUFB;
#pragma unroll
            for (int kk = 0; kk < KCH; kk += 16) {
                uint32_t af[2][2][4];
#pragma unroll
                for (int s = 0; s < 2; s++)
#pragma unroll
                    for (int i = 0; i < 2; i++) {
                        uint32_t off = (uint32_t)((R0 + i * 16 + arow) * 64 +
                                                  (kk + acol) * 2);
                        LDSM4(af[s][i], base + s * ATILE + swz64(off));
                    }
#pragma unroll
                for (int j2 = 0; j2 < NFRAG / 2; j2++) {
                    uint32_t bfm[2][4];
#pragma unroll
                    for (int t = 0; t < 2; t++) {
                        uint32_t off = (uint32_t)((C0w + j2 * 16 + brow) * 64 +
                                                  (kk + bcol) * 2);
                        LDSM4(bfm[t], base + 2 * ATILE + t * WTILE + swz64(off));
                    }
#pragma unroll
                    for (int i = 0; i < 2; i++) {
                        // corrections -> f16 accumulators
                        MMAF16H(cac[i][2 * j2],     af[1][i],
                                bfm[0][0], bfm[0][1]);   // h1*w0
                        MMAF16H(cac[i][2 * j2 + 1], af[1][i],
                                bfm[0][2], bfm[0][3]);
                        MMAF16H(cac[i][2 * j2],     af[0][i],
                                bfm[1][0], bfm[1][1]);   // h0*w1
                        MMAF16H(cac[i][2 * j2 + 1], af[0][i],
                                bfm[1][2], bfm[1][3]);
                        // main -> f32 accumulators
                        MMAF16(acc[i][2 * j2],     af[0][i],
                               bfm[0][0], bfm[0][1]);    // h0*w0
                        MMAF16(acc[i][2 * j2 + 1], af[0][i],
                               bfm[0][2], bfm[0][3]);
                    }
                }
            }
            __syncthreads();
        }

        // ---- per-pass epilogue: fold corrections, bias, store, stats ----
#pragma unroll
        for (int i = 0; i < 2; i++) {
            const int rla = R0 + i * 16 + (lane >> 2);
            float s1a = 0.f, s2a = 0.f, s1b = 0.f, s2b = 0.f;
#pragma unroll
            for (int j = 0; j < NFRAG; j++) {
                __half2 clo = *(__half2*)&cac[i][j][0];   // c0,c1
                __half2 chi = *(__half2*)&cac[i][j][1];   // c2,c3
                acc[i][j][0] += __low2float(clo);
                acc[i][j][1] += __high2float(clo);
                acc[i][j][2] += __low2float(chi);
                acc[i][j][3] += __high2float(chi);
                int cg = n0 + C0w + j * 8 + (lane & 3) * 2;
                acc[i][j][0] += bias_s[cg];
                acc[i][j][1] += bias_s[cg + 1];
                acc[i][j][2] += bias_s[cg];
                acc[i][j][3] += bias_s[cg + 1];
                if (OMODE != 1) {
                    *(float2*)(outf + (r0 + rla) * (int64_t)DOUT + cg) =
                        make_float2(acc[i][j][0], acc[i][j][1]);
                    *(float2*)(outf + (r0 + rla + 8) * (int64_t)DOUT + cg) =
                        make_float2(acc[i][j][2], acc[i][j][3]);
                }
                if (OMODE != 2) {
                    s1a += acc[i][j][0] + acc[i][j][1];
                    s2a += fmaf(acc[i][j][0], acc[i][j][0],
                                acc[i][j][1] * acc[i][j][1]);
                    s1b += acc[i][j][2] + acc[i][j][3];
                    s2b += fmaf(acc[i][j][2], acc[i][j][2],
                                acc[i][j][3] * acc[i][j][3]);
                }
            }
            if (OMODE != 2) {
#pragma unroll
                for (int o = 1; o <= 2; o <<= 1) {
                    s1a += __shfl_xor_sync(0xffffffffu, s1a, o);
                    s2a += __shfl_xor_sync(0xffffffffu, s2a, o);
                    s1b += __shfl_xor_sync(0xffffffffu, s1b, o);
                    s2b += __shfl_xor_sync(0xffffffffu, s2b, o);
                }
                if ((lane & 3) == 0) {
                    atomicAdd(&s1_s[rla], s1a);
                    atomicAdd(&s2_s[rla], s2a);
                    atomicAdd(&s1_s[rla + 8], s1b);
                    atomicAdd(&s2_s[rla + 8], s2b);
                }
            }
        }
    }

    if (OMODE != 2) {
        __syncthreads();
        if (tid < TM) {
            float mu  = s1_s[tid] * (1.0f / DOUT);
            float var = s2_s[tid] * (1.0f / DOUT) - mu * mu;
            s1_s[tid] = mu;
            s2_s[tid] = rsqrtf(var + LN_EPS);
        }
        __syncthreads();
    }

    if (OMODE == 0) {
        const int row = tid >> 1;
        const int cb  = (tid & 1) * (DOUT / 2);
        const float mu = s1_s[row], rs = s2_s[row];
        const float* src = outf + (r0 + row) * (int64_t)DOUT + cb;
        const int64_t od = (r0 + row) * (int64_t)DOUT + cb;
#pragma unroll 2
        for (int c = 0; c < DOUT / 2; c += 8) {
            float4 v0 = *(const float4*)(src + c);
            float4 v1 = *(const float4*)(src + c + 4);
            float x[8] = {v0.x, v0.y, v0.z, v0.w, v1.x, v1.y, v1.z, v1.w};
            __half h0[8], h1[8];
#pragma unroll
            for (int j = 0; j < 8; j++) {
                int cc = cb + c + j;
                float y = fmaxf((x[j] - mu) * rs * go_s[cc] + bo_s[cc], 0.f);
                split2(y, h0[j], h1[j]);
            }
            *(uint4*)(o0 + od + c) =
                make_uint4(pack2(h0[0], h0[1]), pack2(h0[2], h0[3]),
                           pack2(h0[4], h0[5]), pack2(h0[6], h0[7]));
            *(uint4*)(o1 + od + c) =
                make_uint4(pack2(h1[0], h1[1]), pack2(h1[2], h1[3]),
                           pack2(h1[4], h1[5]), pack2(h1[6], h1[7]));
        }
    }

    if (OMODE == 1) {
#pragma unroll
        for (int i = 0; i < 2; i++) {
            const int rla = R0 + i * 16 + (lane >> 2);
            float muA = s1_s[rla], rsA = s2_s[rla];
            float muB = s1_s[rla + 8], rsB = s2_s[rla + 8];
#pragma unroll
            for (int j = 0; j < NFRAG; j++) {
                int cg = C0w + j * 8 + (lane & 3) * 2;
                float ga = go_s[cg], gb = go_s[cg + 1];
                float ba = bo_s[cg], bb = bo_s[cg + 1];
                float v0 = fmaxf((acc[i][j][0] - muA) * rsA * ga + ba, 0.f);
                float v1 = fmaxf((acc[i][j][1] - muA) * rsA * gb + bb, 0.f);
                float v2 = fmaxf((acc[i][j][2] - muB) * rsB * ga + ba, 0.f);
                float v3 = fmaxf((acc[i][j][3] - muB) * rsB * gb + bb, 0.f);
                __half p0[2], p1[2], p2[2], p3[2];
                split2(v0, p0[0], p0[1]);
                split2(v1, p1[0], p1[1]);
                split2(v2, p2[0], p2[1]);
                split2(v3, p3[0], p3[1]);
                int64_t oa = (r0 + rla) * (int64_t)DOUT + cg;
                int64_t ob = (r0 + rla + 8) * (int64_t)DOUT + cg;
                *(uint32_t*)(o0 + oa) = pack2(p0[0], p1[0]);
                *(uint32_t*)(o1 + oa) = pack2(p0[1], p1[1]);
                *(uint32_t*)(o0 + ob) = pack2(p2[0], p3[0]);
                *(uint32_t*)(o1 + ob) = pack2(p2[1], p3[1]);
            }
        }
    }
}

// ============================ prototypes ============================
__global__ void zero_proto_kernel() {
    int t = blockIdx.x * blockDim.x + threadIdx.x;
    if (t < 64 * 32) g_psum[t] = 0.f;
    if (t < 64) g_pcnt[t] = 0.f;
}

__global__ void proto_accum_kernel(const int* __restrict__ labels,
                                   const float* __restrict__ zs) {
    __shared__ float ssum[64 * 32];
    __shared__ float scnt[64];
    int tid = threadIdx.x, lane = tid & 31, warp = tid >> 5;
    for (int t = tid; t < 64 * 32; t += 256) ssum[t] = 0.f;
    if (tid < 64) scnt[tid] = 0.f;
    __syncthreads();
    int rbase = blockIdx.x * 512;
    for (int r = rbase + warp; r < rbase + 512; r += 8) {
        int lab = labels[r];
        lab = max(0, min(63, lab));
        float v = zs[(size_t)r * 32 + lane];
        atomicAdd(&ssum[lab * 32 + lane], v);
        if (lane == 0) atomicAdd(&scnt[lab], 1.f);
    }
    __syncthreads();
    for (int t = tid; t < 64 * 32; t += 256) atomicAdd(&g_psum[t], ssum[t]);
    if (tid < 64) atomicAdd(&g_pcnt[tid], scnt[tid]);
}

__global__ void proto_finalize_kernel() {
    int tid = threadIdx.x;
    for (int i = tid; i < 64 * 32; i += 256) {
        int c = i >> 5;
        g_psum[i] = g_psum[i] / fmaxf(g_pcnt[c], 1.f);
    }
}

// ============================ -cdist ============================
__global__ __launch_bounds__(256) void dist_kernel(const float* __restrict__ zq,
                                                   float* __restrict__ out) {
    __shared__ float ps[64 * 33];
    __shared__ float pn[64];
    __shared__ float qs[16 * 33];
    int tid = threadIdx.x;
    for (int i = tid; i < 64 * 32; i += 256)
        ps[(i >> 5) * 33 + (i & 31)] = g_psum[i];
    int qbase = blockIdx.x * 16;
    for (int i = tid; i < 16 * 32; i += 256) {
        int q = i >> 5, k = i & 31;
        qs[q * 33 + k] = zq[(size_t)(qbase + q) * 32 + k];
    }
    __syncthreads();
    if (tid < 64) {
        float s = 0.f;
#pragma unroll
        for (int k = 0; k < 32; k++) {
            float v = ps[tid * 33 + k];
            s += v * v;
        }
        pn[tid] = s;
    }
    __syncthreads();
    int c = tid & 63;
#pragma unroll
    for (int p = 0; p < 4; p++) {
        int q = p * 4 + (tid >> 6);
        float dot = 0.f, qn = 0.f;
#pragma unroll
        for (int k = 0; k < 32; k++) {
            float a = qs[q * 33 + k];
            float b = ps[c * 33 + k];
            dot = fmaf(a, b, dot);
            qn  = fmaf(a, a, qn);
        }
        float sq = qn + pn[c] - 2.f * dot;
        out[(size_t)(qbase + q) * 64 + c] = -sqrtf(fmaxf(sq, 0.f));
    }
}

// ============================ launch ============================
extern "C" void kernel_launch(void* const* d_in, const int* in_sizes, int n_in,
                              void* d_out, int out_size) {
    const float* sup = (const float*)d_in[0];
    const int*   lab = (const int*)d_in[1];
    const float* qry = (const float*)d_in[2];
    const float* W1 = (const float*)d_in[3];
    const float* b1 = (const float*)d_in[4];
    const float* g1 = (const float*)d_in[5];
    const float* be1 = (const float*)d_in[6];
    const float* W2 = (const float*)d_in[7];
    const float* b2 = (const float*)d_in[8];
    const float* g2 = (const float*)d_in[9];
    const float* be2 = (const float*)d_in[10];
    const float* W3 = (const float*)d_in[11];
    const float* b3 = (const float*)d_in[12];
    const float* g3 = (const float*)d_in[13];
    const float* be3 = (const float*)d_in[14];
    const float* W4 = (const float*)d_in[15];
    const float* b4 = (const float*)d_in[16];

    cudaFuncSetAttribute(layer_kernel<768, 512, 0>,
                         cudaFuncAttributeMaxDynamicSharedMemorySize,
                         smem_of(512));
    cudaFuncSetAttribute(layer_kernel<512, 512, 0>,
                         cudaFuncAttributeMaxDynamicSharedMemorySize,
                         smem_of(512));
    cudaFuncSetAttribute(layer_kernel<512, 128, 1>,
                         cudaFuncAttributeMaxDynamicSharedMemorySize,
                         smem_of(128));
    cudaFuncSetAttribute(layer_kernel<128, 32, 2>,
                         cudaFuncAttributeMaxDynamicSharedMemorySize,
                         smem_of(32));

    float* h = nullptr;
    __half *a0, *a1, *c0, *c1, *p0, *p1;
    cudaGetSymbolAddress((void**)&h, g_h);
    cudaGetSymbolAddress((void**)&a0, g_a0);
    cudaGetSymbolAddress((void**)&a1, g_a1);
    cudaGetSymbolAddress((void**)&c0, g_c0);
    cudaGetSymbolAddress((void**)&c1, g_c1);
    cudaGetSymbolAddress((void**)&p0, g_p0);
    cudaGetSymbolAddress((void**)&p1, g_p1);

    // 1: weight split
    split_w_all<<<(724992 + 255) / 256, 256>>>(W1, W2, W3, W4);
    // 2-3: input converts
    convert_in<<<12288, 256>>>(sup, a0, a1, 32768 * 96);
    convert_in<<<24576, 256>>>(qry, a0 + (int64_t)32768 * 768,
                               a1 + (int64_t)32768 * 768, 65536 * 96);
    // 4: L1 -> h + planes c (LN1+ReLU fused)   [profiled slot]
    layer_kernel<768, 512, 0><<<768, 256, smem_of(512)>>>(
        a0, a1, 0, b1, g1, be1, h, c0, c1);
    // 5: L2 -> h + planes a (LN2+ReLU fused)
    layer_kernel<512, 512, 0><<<768, 256, smem_of(512)>>>(
        c0, c1, 393216, b2, g2, be2, h, a0, a1);
    // 6: L3 -> planes p (LN3+ReLU fused from regs)
    layer_kernel<512, 128, 1><<<768, 256, smem_of(128)>>>(
        a0, a1, 655360, b3, g3, be3, nullptr, p0, p1);
    // 7: L4 -> z fp32 (stride 32)
    layer_kernel<128, 32, 2><<<768, 256, smem_of(32)>>>(
        p0, p1, 720896, b4, nullptr, nullptr, h, nullptr, nullptr);
    // 8+: prototypes + distances
    zero_proto_kernel<<<8, 256>>>();
    proto_accum_kernel<<<64, 256>>>(lab, h);
    proto_finalize_kernel<<<1, 256>>>();
    dist_kernel<<<65536 / 16, 256>>>(h + (size_t)32768 * 32, (float*)d_out);
}

// round 16
// speedup vs baseline: 1.0206x; 1.0206x over previous
#include <cuda_runtime.h>
#include <cuda_fp16.h>
#include <cstdint>

#define LN_EPS 1e-5f

// ============================ PTX helpers ============================
__device__ __forceinline__ uint32_t smem_u32(const void* p) {
    uint32_t a;
    asm("{ .reg .u64 t; cvta.to.shared.u64 t, %1; cvt.u32.u64 %0, t; }"
        : "=r"(a) : "l"(p));
    return a;
}

__device__ __forceinline__ uint32_t swz64(uint32_t off) {
    return off ^ ((off >> 3) & 0x30);   // SW64 swizzle for 64B rows
}

#define LDSM4(r, addr)                                                        \
    asm volatile(                                                             \
        "ldmatrix.sync.aligned.m8n8.x4.shared.b16 {%0,%1,%2,%3}, [%4];"       \
        : "=r"((r)[0]), "=r"((r)[1]), "=r"((r)[2]), "=r"((r)[3])              \
        : "r"(addr))

#define MMAF16(d, a, b0, b1)                                                  \
    asm volatile(                                                             \
        "mma.sync.aligned.m16n8k16.row.col.f32.f16.f16.f32 "                  \
        "{%0,%1,%2,%3}, {%4,%5,%6,%7}, {%8,%9}, {%0,%1,%2,%3};"               \
        : "+f"((d)[0]), "+f"((d)[1]), "+f"((d)[2]), "+f"((d)[3])              \
        : "r"((a)[0]), "r"((a)[1]), "r"((a)[2]), "r"((a)[3]),                 \
          "r"(b0), "r"(b1))

#define CP_ASYNC16(dst, src)                                                  \
    asm volatile("cp.async.cg.shared.global [%0], [%1], 16;"                  \
                 :: "r"(dst), "l"(src))
#define CP_ASYNC_COMMIT() asm volatile("cp.async.commit_group;" ::: "memory")
#define CP_ASYNC_WAIT1()  asm volatile("cp.async.wait_group 1;" ::: "memory")
#define CP_ASYNC_WAIT0()  asm volatile("cp.async.wait_group 0;" ::: "memory")

// ============================ geometry ============================
constexpr int TM    = 128;
constexpr int KCH   = 32;                 // 64 B rows (fp16)
constexpr int ATILE = TM * 64;            // 8192 B per A limb tile

__host__ __device__ constexpr int npass_of(int dout) {
    return dout > 128 ? 128 : dout;
}
__host__ __device__ constexpr int bufb_of(int dout) {
    return 2 * ATILE + 2 * npass_of(dout) * 64;
}
// params block offsets (relative to SM_P)
constexpr int PO_BIAS  = 0;       // 2048
constexpr int PO_GIN   = 2048;    // 2048
constexpr int PO_BEIN  = 4096;    // 2048
constexpr int PO_GO    = 6144;    // 512
constexpr int PO_BO    = 6656;    // 512
constexpr int PO_B4    = 7168;    // 256
constexpr int PO_S1    = 7424;    // 512
constexpr int PO_S2    = 7936;    // 512
constexpr int PO_STATS = 8448;    // 1024 (float2 x 128)
constexpr int PB       = 9472;
__host__ __device__ constexpr int smem_of(int dout, int mode) {
    return 2 * bufb_of(dout) + PB + (mode == 2 ? 16384 : 0);
}

// ============================ scratch ============================
__device__ __align__(256) float  g_h0[98304ull * 512];
__device__ __align__(256) float  g_h1[98304ull * 512];
__device__ float2 g_sa[98304];
__device__ float2 g_sb[98304];
__device__ __align__(256) __half g_w0[724992];
__device__ __align__(256) __half g_w1[724992];
__device__ float g_psum[64 * 32];
__device__ float g_pcnt[64];

// ============================ 2-way fp16 split ============================
__device__ __forceinline__ void split2(float a, __half& h0, __half& h1) {
    h0 = __float2half_rn(a);
    h1 = __float2half_rn(a - __half2float(h0));
}
__device__ __forceinline__ uint32_t pack2(__half a, __half b) {
    return ((uint32_t)__half_as_ushort(b) << 16) | (uint32_t)__half_as_ushort(a);
}

// ============================ W prep ============================
__global__ void split_w_all(const float* __restrict__ W1,
                            const float* __restrict__ W2,
                            const float* __restrict__ W3,
                            const float* __restrict__ W4) {
    int i = blockIdx.x * 256 + threadIdx.x;
    if (i >= 724992) return;
    float v;
    if (i < 393216) v = W1[i];
    else if (i < 655360) v = W2[i - 393216];
    else if (i < 720896) v = W3[i - 655360];
    else v = W4[i - 720896];
    __half h0, h1;
    split2(v, h0, h1);
    g_w0[i] = h0;
    g_w1[i] = h1;
}

// ============================ A staging (fp32 -> split tiles) ============
template <int DIN, bool NORM>
__device__ __forceinline__ void stage_A(
    char* sm, int dstOff, const float* __restrict__ A, int64_t r0, int k0,
    const float2* stats_s, const float* gin_s, const float* bein_s, int tid) {
#pragma unroll
    for (int it = 0; it < 4; it++) {
        int idx = tid + it * 256;       // 0..1023
        int row = idx >> 3, q = idx & 7;
        float4 v = *(const float4*)(A + (r0 + row) * (int64_t)DIN + k0 + q * 4);
        float x[4] = {v.x, v.y, v.z, v.w};
        if (NORM) {
            float2 st = stats_s[row];
#pragma unroll
            for (int j = 0; j < 4; j++) {
                int c = k0 + q * 4 + j;
                x[j] = fmaxf((x[j] - st.x) * st.y * gin_s[c] + bein_s[c], 0.f);
            }
        }
        __half h0[4], h1[4];
#pragma unroll
        for (int j = 0; j < 4; j++) split2(x[j], h0[j], h1[j]);
        uint32_t off = swz64((uint32_t)(row * 64 + q * 8));
        *(uint2*)(sm + dstOff + off) =
            make_uint2(pack2(h0[0], h0[1]), pack2(h0[2], h0[3]));
        *(uint2*)(sm + dstOff + 8192 + off) =
            make_uint2(pack2(h1[0], h1[1]), pack2(h1[2], h1[3]));
    }
}

// ============================ W chunk prefetch (cp.async) ===============
template <int DIN, int NPASS>
__device__ __forceinline__ void issue_W(uint32_t smb, int buf, int n0, int k0,
                                        const __half* w0, const __half* w1,
                                        int tid) {
    constexpr int BUFB  = bufb_of(NPASS);
    constexpr int WTILE = NPASS * 64;
    const uint32_t base = smb + buf * BUFB + 2 * ATILE;
    const __half* wp[2] = {w0, w1};
#pragma unroll
    for (int t = 0; t < 2; t++) {
        for (int i = tid; i < NPASS * 4; i += 256) {
            int r = i >> 2, q = i & 3;
            const void* src = wp[t] + (n0 + r) * (int64_t)DIN + k0 + q * 8;
            uint32_t dst = base + t * WTILE + swz64((uint32_t)(r * 64 + q * 16));
            CP_ASYNC16(dst, src);
        }
    }
}

// ============================ layer kernel ============================
// MODE 0: plain input -> fp32 h + stats (L1)
// MODE 1: LN input    -> fp32 h + stats (L2)
// MODE 2: LN input    -> fused LN3+ReLU+split + in-kernel L4 -> z (L3+L4)
template <int DIN, int DOUT, int MODE>
__global__ __launch_bounds__(256, 2) void layer_kernel(
    const float* __restrict__ A, const float2* __restrict__ stats_in,
    const float* __restrict__ gin, const float* __restrict__ bein,
    int w_off, const float* __restrict__ bias,
    const float* __restrict__ go, const float* __restrict__ bo,
    const float* __restrict__ b4,
    float* __restrict__ outf, float2* __restrict__ stats_out) {
    extern __shared__ char sm[];
    const uint32_t smb = smem_u32(sm);
    const int tid  = threadIdx.x;
    const int lane = tid & 31;
    const int wid  = tid >> 5;
    const int64_t r0 = (int64_t)blockIdx.x * TM;

    constexpr bool NORM = (MODE >= 1);
    constexpr int NPASS = npass_of(DOUT);
    constexpr int NT    = DOUT / NPASS;
    constexpr int WC    = NPASS / 2;
    constexpr int NFRAG = WC / 8;
    constexpr int NCH   = DIN / KCH;
    constexpr int BUFB  = bufb_of(DOUT);
    constexpr int WTILE = NPASS * 64;
    constexpr int SM_P  = 2 * BUFB;
    constexpr int W4OFF = SM_P + PB;
    static_assert(MODE != 2 || NT == 1, "fused L4 needs NT==1");
    static_assert(NFRAG >= 2, "need at least 2 fragments per warp");

    const int wr  = wid >> 1;
    const int wc  = wid & 1;
    const int R0  = wr * 32;
    const int C0w = wc * WC;

    const int sub  = lane >> 3;
    const int arow = (sub & 1) * 8 + (lane & 7);
    const int acol = (sub >> 1) * 8;
    const int brow = (sub >> 1) * 8 + (lane & 7);
    const int bcol = (sub & 1) * 8;

    float*  bias_s  = (float*)(sm + SM_P + PO_BIAS);
    float*  gin_s   = (float*)(sm + SM_P + PO_GIN);
    float*  bein_s  = (float*)(sm + SM_P + PO_BEIN);
    float*  go_s    = (float*)(sm + SM_P + PO_GO);
    float*  bo_s    = (float*)(sm + SM_P + PO_BO);
    float*  b4_s    = (float*)(sm + SM_P + PO_B4);
    float*  s1_s    = (float*)(sm + SM_P + PO_S1);
    float*  s2_s    = (float*)(sm + SM_P + PO_S2);
    float2* stats_s = (float2*)(sm + SM_P + PO_STATS);

    for (int i = tid; i < DOUT; i += 256) bias_s[i] = bias[i];
    if (NORM) {
        for (int i = tid; i < DIN; i += 256) {
            gin_s[i]  = gin[i];
            bein_s[i] = bein[i];
        }
        if (tid < TM) stats_s[tid] = stats_in[r0 + tid];
    }
    if (MODE == 2) {
        for (int i = tid; i < DOUT; i += 256) {
            go_s[i] = go[i];
            bo_s[i] = bo[i];
        }
        if (tid < 32) b4_s[tid] = b4[tid];
        // stage W4 limb tiles [32 x 128] -> 4 kchunks x 2 limbs x 2KB
#pragma unroll
        for (int it = 0; it < 2; it++) {
            int idx = tid + it * 256;          // 0..511
            int row = idx >> 4, u = idx & 15;
            int kc = u >> 2, kin16 = (u & 3) * 16;
#pragma unroll
            for (int limb = 0; limb < 2; limb++) {
                const __half* src =
                    (limb ? g_w1 : g_w0) + 720896 + row * 128 + u * 8;
                uint32_t dst = W4OFF + (kc * 2 + limb) * 2048 +
                               swz64((uint32_t)(row * 64 + kin16));
                *(uint4*)(sm + dst) = *(const uint4*)src;
            }
        }
    }
    if (tid < TM) {
        s1_s[tid] = 0.f;
        s2_s[tid] = 0.f;
    }
    __syncthreads();

    const __half* w0 = g_w0 + w_off;
    const __half* w1 = g_w1 + w_off;

    float acc[2][NFRAG][4];

    for (int nt = 0; nt < NT; nt++) {
#pragma unroll
        for (int i = 0; i < 2; i++)
#pragma unroll
            for (int j = 0; j < NFRAG; j++)
#pragma unroll
                for (int q = 0; q < 4; q++) acc[i][j][q] = 0.f;

        const int n0 = nt * NPASS;
        stage_A<DIN, NORM>(sm, 0, A, r0, 0, stats_s, gin_s, bein_s, tid);
        issue_W<DIN, NPASS>(smb, 0, n0, 0, w0, w1, tid);
        CP_ASYNC_COMMIT();

        for (int ch = 0; ch < NCH; ch++) {
            if (ch + 1 < NCH) {
                issue_W<DIN, NPASS>(smb, (ch + 1) & 1, n0, (ch + 1) * KCH,
                                    w0, w1, tid);
                CP_ASYNC_COMMIT();
                stage_A<DIN, NORM>(sm, ((ch + 1) & 1) * BUFB, A, r0,
                                   (ch + 1) * KCH, stats_s, gin_s, bein_s,
                                   tid);
                CP_ASYNC_WAIT1();
            } else {
                CP_ASYNC_WAIT0();
            }
            __syncthreads();

            const uint32_t base = smb + (ch & 1) * BUFB;
#pragma unroll
            for (int kk = 0; kk < KCH; kk += 16) {
                uint32_t af[2][2][4];
#pragma unroll
                for (int s = 0; s < 2; s++)
#pragma unroll
                    for (int i = 0; i < 2; i++) {
                        uint32_t off = (uint32_t)((R0 + i * 16 + arow) * 64 +
                                                  (kk + acol) * 2);
                        LDSM4(af[s][i], base + s * ATILE + swz64(off));
                    }
#pragma unroll
                for (int j2 = 0; j2 < NFRAG / 2; j2++) {
                    uint32_t bfm[2][4];
#pragma unroll
                    for (int t = 0; t < 2; t++) {
                        uint32_t off = (uint32_t)((C0w + j2 * 16 + brow) * 64 +
                                                  (kk + bcol) * 2);
                        LDSM4(bfm[t], base + 2 * ATILE + t * WTILE + swz64(off));
                    }
                    constexpr int PS[3] = {1, 0, 0};
                    constexpr int PT[3] = {0, 1, 0};
#pragma unroll
                    for (int p = 0; p < 3; p++) {
                        const int s = PS[p], t = PT[p];
#pragma unroll
                        for (int i = 0; i < 2; i++) {
                            MMAF16(acc[i][2 * j2],     af[s][i],
                                   bfm[t][0], bfm[t][1]);
                            MMAF16(acc[i][2 * j2 + 1], af[s][i],
                                   bfm[t][2], bfm[t][3]);
                        }
                    }
                }
            }
            __syncthreads();
        }

        // ---- per-pass epilogue: bias, (fp32 store), stats ----
#pragma unroll
        for (int i = 0; i < 2; i++) {
            const int rla = R0 + i * 16 + (lane >> 2);
            float s1a = 0.f, s2a = 0.f, s1b = 0.f, s2b = 0.f;
#pragma unroll
            for (int j = 0; j < NFRAG; j++) {
                int cg = n0 + C0w + j * 8 + (lane & 3) * 2;
                acc[i][j][0] += bias_s[cg];
                acc[i][j][1] += bias_s[cg + 1];
                acc[i][j][2] += bias_s[cg];
                acc[i][j][3] += bias_s[cg + 1];
                if (MODE != 2) {
                    *(float2*)(outf + (r0 + rla) * (int64_t)DOUT + cg) =
                        make_float2(acc[i][j][0], acc[i][j][1]);
                    *(float2*)(outf + (r0 + rla + 8) * (int64_t)DOUT + cg) =
                        make_float2(acc[i][j][2], acc[i][j][3]);
                }
                s1a += acc[i][j][0] + acc[i][j][1];
                s2a += fmaf(acc[i][j][0], acc[i][j][0],
                            acc[i][j][1] * acc[i][j][1]);
                s1b += acc[i][j][2] + acc[i][j][3];
                s2b += fmaf(acc[i][j][2], acc[i][j][2],
                            acc[i][j][3] * acc[i][j][3]);
            }
#pragma unroll
            for (int o = 1; o <= 2; o <<= 1) {
                s1a += __shfl_xor_sync(0xffffffffu, s1a, o);
                s2a += __shfl_xor_sync(0xffffffffu, s2a, o);
                s1b += __shfl_xor_sync(0xffffffffu, s1b, o);
                s2b += __shfl_xor_sync(0xffffffffu, s2b, o);
            }
            if ((lane & 3) == 0) {
                atomicAdd(&s1_s[rla], s1a);
                atomicAdd(&s2_s[rla], s2a);
                atomicAdd(&s1_s[rla + 8], s1b);
                atomicAdd(&s2_s[rla + 8], s2b);
            }
        }
    }

    __syncthreads();
    if (tid < TM) {
        float mu  = s1_s[tid] * (1.0f / DOUT);
        float var = s2_s[tid] * (1.0f / DOUT) - mu * mu;
        float rs  = rsqrtf(var + LN_EPS);
        if (MODE != 2) {
            stats_out[r0 + tid] = make_float2(mu, rs);
        } else {
            s1_s[tid] = mu;
            s2_s[tid] = rs;
        }
    }

    if (MODE == 2) {
        __syncthreads();
        // LN3+ReLU+split from regs -> h3 limb tiles in (dead) buffer region
#pragma unroll
        for (int i = 0; i < 2; i++) {
            const int rla = R0 + i * 16 + (lane >> 2);
            float muA = s1_s[rla], rsA = s2_s[rla];
            float muB = s1_s[rla + 8], rsB = s2_s[rla + 8];
#pragma unroll
            for (int j = 0; j < NFRAG; j++) {
                int cg = C0w + j * 8 + (lane & 3) * 2;
                float ga = go_s[cg], gb = go_s[cg + 1];
                float ba = bo_s[cg], bb = bo_s[cg + 1];
                float v0 = fmaxf((acc[i][j][0] - muA) * rsA * ga + ba, 0.f);
                float v1 = fmaxf((acc[i][j][1] - muA) * rsA * gb + bb, 0.f);
                float v2 = fmaxf((acc[i][j][2] - muB) * rsB * ga + ba, 0.f);
                float v3 = fmaxf((acc[i][j][3] - muB) * rsB * gb + bb, 0.f);
                __half p0[2], p1[2], p2[2], p3[2];
                split2(v0, p0[0], p0[1]);
                split2(v1, p1[0], p1[1]);
                split2(v2, p2[0], p2[1]);
                split2(v3, p3[0], p3[1]);
                int kc = cg >> 5, kin = cg & 31;
                uint32_t oa = kc * 16384 + swz64((uint32_t)(rla * 64 + kin * 2));
                uint32_t ob = kc * 16384 +
                              swz64((uint32_t)((rla + 8) * 64 + kin * 2));
                *(uint32_t*)(sm + oa)        = pack2(p0[0], p1[0]);
                *(uint32_t*)(sm + oa + 8192) = pack2(p0[1], p1[1]);
                *(uint32_t*)(sm + ob)        = pack2(p2[0], p3[0]);
                *(uint32_t*)(sm + ob + 8192) = pack2(p2[1], p3[1]);
            }
        }
        __syncthreads();

        // ---- in-kernel L4: z[128x32] = h3[128x128] @ W4^T + b4 ----
        float a4[2][2][4];
#pragma unroll
        for (int i = 0; i < 2; i++)
#pragma unroll
            for (int jf = 0; jf < 2; jf++)
#pragma unroll
                for (int q = 0; q < 4; q++) a4[i][jf][q] = 0.f;
#pragma unroll
        for (int kc = 0; kc < 4; kc++)
#pragma unroll
            for (int kk = 0; kk < 32; kk += 16) {
                uint32_t af4[2][2][4];
#pragma unroll
                for (int s = 0; s < 2; s++)
#pragma unroll
                    for (int i = 0; i < 2; i++) {
                        uint32_t off = (uint32_t)((R0 + i * 16 + arow) * 64 +
                                                  (kk + acol) * 2);
                        LDSM4(af4[s][i],
                              smb + kc * 16384 + s * 8192 + swz64(off));
                    }
                uint32_t bf4[2][4];
#pragma unroll
                for (int t = 0; t < 2; t++) {
                    uint32_t off = (uint32_t)((wc * 16 + brow) * 64 +
                                              (kk + bcol) * 2);
                    LDSM4(bf4[t],
                          smb + W4OFF + (kc * 2 + t) * 2048 + swz64(off));
                }
                constexpr int PS[3] = {1, 0, 0};
                constexpr int PT[3] = {0, 1, 0};
#pragma unroll
                for (int p = 0; p < 3; p++) {
                    const int s = PS[p], t = PT[p];
#pragma unroll
                    for (int i = 0; i < 2; i++) {
                        MMAF16(a4[i][0], af4[s][i], bf4[t][0], bf4[t][1]);
                        MMAF16(a4[i][1], af4[s][i], bf4[t][2], bf4[t][3]);
                    }
                }
            }
#pragma unroll
        for (int i = 0; i < 2; i++) {
            const int rla = R0 + i * 16 + (lane >> 2);
#pragma unroll
            for (int jf = 0; jf < 2; jf++) {
                int c4 = wc * 16 + jf * 8 + (lane & 3) * 2;
                float bb0 = b4_s[c4], bb1 = b4_s[c4 + 1];
                *(float2*)(outf + (r0 + rla) * 32 + c4) =
                    make_float2(a4[i][jf][0] + bb0, a4[i][jf][1] + bb1);
                *(float2*)(outf + (r0 + rla + 8) * 32 + c4) =
                    make_float2(a4[i][jf][2] + bb0, a4[i][jf][3] + bb1);
            }
        }
    }
}

// ============================ prototypes ============================
__global__ void zero_proto_kernel() {
    int t = blockIdx.x * blockDim.x + threadIdx.x;
    if (t < 64 * 32) g_psum[t] = 0.f;
    if (t < 64) g_pcnt[t] = 0.f;
}

__global__ void proto_accum_kernel(const int* __restrict__ labels,
                                   const float* __restrict__ zs) {
    __shared__ float ssum[64 * 32];
    __shared__ float scnt[64];
    int tid = threadIdx.x, lane = tid & 31, warp = tid >> 5;
    for (int t = tid; t < 64 * 32; t += 256) ssum[t] = 0.f;
    if (tid < 64) scnt[tid] = 0.f;
    __syncthreads();
    int rbase = blockIdx.x * 512;
    for (int r = rbase + warp; r < rbase + 512; r += 8) {
        int lab = labels[r];
        lab = max(0, min(63, lab));
        float v = zs[(size_t)r * 32 + lane];
        atomicAdd(&ssum[lab * 32 + lane], v);
        if (lane == 0) atomicAdd(&scnt[lab], 1.f);
    }
    __syncthreads();
    for (int t = tid; t < 64 * 32; t += 256) atomicAdd(&g_psum[t], ssum[t]);
    if (tid < 64) atomicAdd(&g_pcnt[tid], scnt[tid]);
}

__global__ void proto_finalize_kernel() {
    int tid = threadIdx.x;
    for (int i = tid; i < 64 * 32; i += 256) {
        int c = i >> 5;
        g_psum[i] = g_psum[i] / fmaxf(g_pcnt[c], 1.f);
    }
}

// ============================ -cdist ============================
__global__ __launch_bounds__(256) void dist_kernel(const float* __restrict__ zq,
                                                   float* __restrict__ out) {
    __shared__ float ps[64 * 33];
    __shared__ float pn[64];
    __shared__ float qs[16 * 33];
    int tid = threadIdx.x;
    for (int i = tid; i < 64 * 32; i += 256)
        ps[(i >> 5) * 33 + (i & 31)] = g_psum[i];
    int qbase = blockIdx.x * 16;
    for (int i = tid; i < 16 * 32; i += 256) {
        int q = i >> 5, k = i & 31;
        qs[q * 33 + k] = zq[(size_t)(qbase + q) * 32 + k];
    }
    __syncthreads();
    if (tid < 64) {
        float s = 0.f;
#pragma unroll
        for (int k = 0; k < 32; k++) {
            float v = ps[tid * 33 + k];
            s += v * v;
        }
        pn[tid] = s;
    }
    __syncthreads();
    int c = tid & 63;
#pragma unroll
    for (int p = 0; p < 4; p++) {
        int q = p * 4 + (tid >> 6);
        float dot = 0.f, qn = 0.f;
#pragma unroll
        for (int k = 0; k < 32; k++) {
            float a = qs[q * 33 + k];
            float b = ps[c * 33 + k];
            dot = fmaf(a, b, dot);
            qn  = fmaf(a, a, qn);
        }
        float sq = qn + pn[c] - 2.f * dot;
        out[(size_t)(qbase + q) * 64 + c] = -sqrtf(fmaxf(sq, 0.f));
    }
}

// ============================ launch ============================
extern "C" void kernel_launch(void* const* d_in, const int* in_sizes, int n_in,
                              void* d_out, int out_size) {
    const float* sup = (const float*)d_in[0];
    const int*   lab = (const int*)d_in[1];
    const float* qry = (const float*)d_in[2];
    const float* W1 = (const float*)d_in[3];
    const float* b1 = (const float*)d_in[4];
    const float* g1 = (const float*)d_in[5];
    const float* be1 = (const float*)d_in[6];
    const float* W2 = (const float*)d_in[7];
    const float* b2 = (const float*)d_in[8];
    const float* g2 = (const float*)d_in[9];
    const float* be2 = (const float*)d_in[10];
    const float* W3 = (const float*)d_in[11];
    const float* b3 = (const float*)d_in[12];
    const float* g3 = (const float*)d_in[13];
    const float* be3 = (const float*)d_in[14];
    const float* W4 = (const float*)d_in[15];
    const float* b4 = (const float*)d_in[16];

    cudaFuncSetAttribute(layer_kernel<768, 512, 0>,
                         cudaFuncAttributeMaxDynamicSharedMemorySize,
                         smem_of(512, 0));
    cudaFuncSetAttribute(layer_kernel<512, 512, 1>,
                         cudaFuncAttributeMaxDynamicSharedMemorySize,
                         smem_of(512, 1));
    cudaFuncSetAttribute(layer_kernel<512, 128, 2>,
                         cudaFuncAttributeMaxDynamicSharedMemorySize,
                         smem_of(128, 2));

    float*  h0 = nullptr;
    float*  h1 = nullptr;
    float2* sa = nullptr;
    float2* sb = nullptr;
    cudaGetSymbolAddress((void**)&h0, g_h0);
    cudaGetSymbolAddress((void**)&h1, g_h1);
    cudaGetSymbolAddress((void**)&sa, g_sa);
    cudaGetSymbolAddress((void**)&sb, g_sb);

    // 1: weight split
    split_w_all<<<(724992 + 255) / 256, 256>>>(W1, W2, W3, W4);
    // 2: L1 support -> h0 + stats_a
    layer_kernel<768, 512, 0><<<256, 256, smem_of(512, 0)>>>(
        sup, nullptr, nullptr, nullptr, 0, b1, nullptr, nullptr, nullptr,
        h0, sa);
    // 3: L1 query
    layer_kernel<768, 512, 0><<<512, 256, smem_of(512, 0)>>>(
        qry, nullptr, nullptr, nullptr, 0, b1, nullptr, nullptr, nullptr,
        h0 + (int64_t)32768 * 512, sa + 32768);
    // 4: L2 (LN1 applied on staging) -> h1 + stats_b   [profiled slot]
    layer_kernel<512, 512, 1><<<768, 256, smem_of(512, 1)>>>(
        h0, sa, g1, be1, 393216, b2, nullptr, nullptr, nullptr, h1, sb);
    // 5: L3 (LN2 on staging) + fused LN3/ReLU + in-kernel L4 -> z in h0
    layer_kernel<512, 128, 2><<<768, 256, smem_of(128, 2)>>>(
        h1, sb, g2, be2, 655360, b3, g3, be3, b4, h0, nullptr);
    // 6+: prototypes + distances
    zero_proto_kernel<<<8, 256>>>();
    proto_accum_kernel<<<64, 256>>>(lab, h0);
    proto_finalize_kernel<<<1, 256>>>();
    dist_kernel<<<65536 / 16, 256>>>(h0 + (size_t)32768 * 32, (float*)d_out);
}

// round 17
// speedup vs baseline: 1.1631x; 1.1397x over previous
#include <cuda_runtime.h>
#include <cuda_fp16.h>
#include <cstdint>

#define LN_EPS 1e-5f

// ============================ PTX helpers ============================
__device__ __forceinline__ uint32_t smem_u32(const void* p) {
    uint32_t a;
    asm("{ .reg .u64 t; cvta.to.shared.u64 t, %1; cvt.u32.u64 %0, t; }"
        : "=r"(a) : "l"(p));
    return a;
}

__device__ __forceinline__ uint32_t swz64(uint32_t off) {
    return off ^ ((off >> 3) & 0x30);   // SW64 swizzle for 64B rows
}

#define LDSM4(r, addr)                                                        \
    asm volatile(                                                             \
        "ldmatrix.sync.aligned.m8n8.x4.shared.b16 {%0,%1,%2,%3}, [%4];"       \
        : "=r"((r)[0]), "=r"((r)[1]), "=r"((r)[2]), "=r"((r)[3])              \
        : "r"(addr))

#define MMAF16(d, a, b0, b1)                                                  \
    asm volatile(                                                             \
        "mma.sync.aligned.m16n8k16.row.col.f32.f16.f16.f32 "                  \
        "{%0,%1,%2,%3}, {%4,%5,%6,%7}, {%8,%9}, {%0,%1,%2,%3};"               \
        : "+f"((d)[0]), "+f"((d)[1]), "+f"((d)[2]), "+f"((d)[3])              \
        : "r"((a)[0]), "r"((a)[1]), "r"((a)[2]), "r"((a)[3]),                 \
          "r"(b0), "r"(b1))

#define CP_ASYNC16(dst, src)                                                  \
    asm volatile("cp.async.cg.shared.global [%0], [%1], 16;"                  \
                 :: "r"(dst), "l"(src))
#define CP_ASYNC_COMMIT() asm volatile("cp.async.commit_group;" ::: "memory")
#define CP_ASYNC_WAIT1()  asm volatile("cp.async.wait_group 1;" ::: "memory")
#define CP_ASYNC_WAIT0()  asm volatile("cp.async.wait_group 0;" ::: "memory")

// ============================ geometry ============================
constexpr int TM    = 128;
constexpr int KCH   = 32;                 // 64 B rows (fp16)
constexpr int ATILE = TM * 64;            // 8192 B per A limb tile

__host__ __device__ constexpr int npass_of(int dout) {
    return dout > 128 ? 128 : dout;
}
__host__ __device__ constexpr int bufb_of(int dout) {
    return 2 * ATILE + 2 * npass_of(dout) * 64;
}
// params block: bias 2048 | go 2048 | bo 2048 | b4 256 | s1 512 | s2 512
constexpr int PO_GO   = 2048;
constexpr int PO_BO   = 4096;
constexpr int PO_B4   = 6144;
constexpr int PO_S1   = 6400;
constexpr int PO_S2   = 6912;
constexpr int PB      = 7424;
__host__ __device__ constexpr int smem_of(int dout, int mode) {
    return 2 * bufb_of(dout) + PB + (mode == 1 ? 16384 : 0);
}

// ============================ scratch ============================
__device__ __align__(256) float  g_h[98304ull * 512];
__device__ __align__(256) __half g_a0[98304ull * 768];
__device__ __align__(256) __half g_a1[98304ull * 768];
__device__ __align__(256) __half g_c0[98304ull * 512];
__device__ __align__(256) __half g_c1[98304ull * 512];
__device__ __align__(256) __half g_w0[724992];
__device__ __align__(256) __half g_w1[724992];
__device__ float g_psum[64 * 32];
__device__ float g_pcnt[64];

// ============================ 2-way fp16 split ============================
__device__ __forceinline__ void split2(float a, __half& h0, __half& h1) {
    h0 = __float2half_rn(a);
    h1 = __float2half_rn(a - __half2float(h0));
}
__device__ __forceinline__ uint32_t pack2(__half a, __half b) {
    return ((uint32_t)__half_as_ushort(b) << 16) | (uint32_t)__half_as_ushort(a);
}

// ============================ W prep (+ proto zero) ============================
__global__ void split_w_all(const float* __restrict__ W1,
                            const float* __restrict__ W2,
                            const float* __restrict__ W3,
                            const float* __restrict__ W4) {
    int i = blockIdx.x * 256 + threadIdx.x;
    if (i < 64 * 32) g_psum[i] = 0.f;
    if (i < 64) g_pcnt[i] = 0.f;
    if (i >= 724992) return;
    float v;
    if (i < 393216) v = W1[i];
    else if (i < 655360) v = W2[i - 393216];
    else if (i < 720896) v = W3[i - 655360];
    else v = W4[i - 720896];
    __half h0, h1;
    split2(v, h0, h1);
    g_w0[i] = h0;
    g_w1[i] = h1;
}

// ============================ input convert ============================
__global__ __launch_bounds__(256) void convert_in(
    const float* __restrict__ x, __half* __restrict__ o0,
    __half* __restrict__ o1, int total8) {
    int i = blockIdx.x * 256 + threadIdx.x;
    if (i >= total8) return;
    int r = i / 96;
    int q = i - r * 96;
    const float* src = x + (int64_t)r * 768 + q * 8;
    float4 v0 = *(const float4*)src;
    float4 v1 = *(const float4*)(src + 4);
    float xx[8] = {v0.x, v0.y, v0.z, v0.w, v1.x, v1.y, v1.z, v1.w};
    __half h0[8], h1[8];
#pragma unroll
    for (int j = 0; j < 8; j++) split2(xx[j], h0[j], h1[j]);
    int64_t o = (int64_t)r * 768 + q * 8;
    *(uint4*)(o0 + o) = make_uint4(pack2(h0[0], h0[1]), pack2(h0[2], h0[3]),
                                   pack2(h0[4], h0[5]), pack2(h0[6], h0[7]));
    *(uint4*)(o1 + o) = make_uint4(pack2(h1[0], h1[1]), pack2(h1[2], h1[3]),
                                   pack2(h1[4], h1[5]), pack2(h1[6], h1[7]));
}

// ============================ chunk prefetch ============================
template <int DIN, int NPASS>
__device__ __forceinline__ void issue_chunk(
    uint32_t smb, int buf, int64_t r0, int n0, int k0,
    const __half* __restrict__ a0, const __half* __restrict__ a1,
    const __half* w0, const __half* w1, int tid) {
    constexpr int BUFB  = bufb_of(NPASS);
    constexpr int WTILE = NPASS * 64;
    const uint32_t base = smb + buf * BUFB;
    const __half* ap[2] = {a0, a1};
    const __half* wp[2] = {w0, w1};
#pragma unroll
    for (int s = 0; s < 2; s++) {
#pragma unroll
        for (int it = 0; it < 2; it++) {
            int i = tid + it * 256;
            int r = i >> 2, q = i & 3;
            const void* src = ap[s] + (r0 + r) * (int64_t)DIN + k0 + q * 8;
            uint32_t dst = base + s * ATILE + swz64((uint32_t)(r * 64 + q * 16));
            CP_ASYNC16(dst, src);
        }
    }
#pragma unroll
    for (int t = 0; t < 2; t++) {
        for (int i = tid; i < NPASS * 4; i += 256) {
            int r = i >> 2, q = i & 3;
            const void* src = wp[t] + (n0 + r) * (int64_t)DIN + k0 + q * 8;
            uint32_t dst = base + 2 * ATILE + t * WTILE +
                           swz64((uint32_t)(r * 64 + q * 16));
            CP_ASYNC16(dst, src);
        }
    }
}

// ============================ layer kernel ============================
// OMODE 0: fp32 h out + LN stats + fused phase-2 LN/ReLU/split -> planes
// OMODE 1: fused LN3/ReLU/split to SMEM + in-kernel L4 -> z fp32 (L3+L4)
template <int DIN, int DOUT, int OMODE>
__global__ __launch_bounds__(256, 2) void layer_kernel(
    const __half* __restrict__ a0, const __half* __restrict__ a1, int w_off,
    const float* __restrict__ bias,
    const float* __restrict__ go, const float* __restrict__ bo,
    const float* __restrict__ b4,
    float* __restrict__ outf,
    __half* __restrict__ o0, __half* __restrict__ o1) {
    extern __shared__ char sm[];
    const uint32_t smb = smem_u32(sm);
    const int tid  = threadIdx.x;
    const int lane = tid & 31;
    const int wid  = tid >> 5;
    const int64_t r0 = (int64_t)blockIdx.x * TM;

    constexpr int NPASS = npass_of(DOUT);
    constexpr int NT    = DOUT / NPASS;
    constexpr int WC    = NPASS / 2;
    constexpr int NFRAG = WC / 8;
    constexpr int NCH   = DIN / KCH;
    constexpr int BUFB  = bufb_of(DOUT);
    constexpr int WTILE = NPASS * 64;
    constexpr int SM_P  = 2 * BUFB;
    constexpr int W4OFF = SM_P + PB;
    static_assert(OMODE != 1 || NT == 1, "fused L4 needs NT==1");
    static_assert(NFRAG >= 2, "need at least 2 fragments per warp");

    const int wr  = wid >> 1;
    const int wc  = wid & 1;
    const int R0  = wr * 32;
    const int C0w = wc * WC;

    const int sub  = lane >> 3;
    const int arow = (sub & 1) * 8 + (lane & 7);
    const int acol = (sub >> 1) * 8;
    const int brow = (sub >> 1) * 8 + (lane & 7);
    const int bcol = (sub & 1) * 8;

    float* bias_s = (float*)(sm + SM_P);
    float* go_s   = (float*)(sm + SM_P + PO_GO);
    float* bo_s   = (float*)(sm + SM_P + PO_BO);
    float* b4_s   = (float*)(sm + SM_P + PO_B4);
    float* s1_s   = (float*)(sm + SM_P + PO_S1);
    float* s2_s   = (float*)(sm + SM_P + PO_S2);

    for (int i = tid; i < DOUT; i += 256) {
        bias_s[i] = bias[i];
        go_s[i] = go[i];
        bo_s[i] = bo[i];
    }
    if (OMODE == 1) {
        if (tid < 32) b4_s[tid] = b4[tid];
        // stage W4 limb tiles [32 x 128] -> 4 kchunks x 2 limbs x 2KB
#pragma unroll
        for (int it = 0; it < 2; it++) {
            int idx = tid + it * 256;          // 0..511
            int row = idx >> 4, u = idx & 15;
            int kc = u >> 2, kin16 = (u & 3) * 16;
#pragma unroll
            for (int limb = 0; limb < 2; limb++) {
                const __half* src =
                    (limb ? g_w1 : g_w0) + 720896 + row * 128 + u * 8;
                uint32_t dst = W4OFF + (kc * 2 + limb) * 2048 +
                               swz64((uint32_t)(row * 64 + kin16));
                *(uint4*)(sm + dst) = *(const uint4*)src;
            }
        }
    }
    if (tid < TM) {
        s1_s[tid] = 0.f;
        s2_s[tid] = 0.f;
    }
    __syncthreads();

    const __half* w0 = g_w0 + w_off;
    const __half* w1 = g_w1 + w_off;

    float acc[2][NFRAG][4];

    for (int nt = 0; nt < NT; nt++) {
#pragma unroll
        for (int i = 0; i < 2; i++)
#pragma unroll
            for (int j = 0; j < NFRAG; j++)
#pragma unroll
                for (int q = 0; q < 4; q++) acc[i][j][q] = 0.f;

        const int n0 = nt * NPASS;
        issue_chunk<DIN, NPASS>(smb, 0, r0, n0, 0, a0, a1, w0, w1, tid);
        CP_ASYNC_COMMIT();

        for (int ch = 0; ch < NCH; ch++) {
            if (ch + 1 < NCH) {
                issue_chunk<DIN, NPASS>(smb, (ch + 1) & 1, r0, n0,
                                        (ch + 1) * KCH, a0, a1, w0, w1, tid);
                CP_ASYNC_COMMIT();
                CP_ASYNC_WAIT1();
            } else {
                CP_ASYNC_WAIT0();
            }
            __syncthreads();

            const uint32_t base = smb + (ch & 1) * BUFB;
#pragma unroll
            for (int kk = 0; kk < KCH; kk += 16) {
                uint32_t af[2][2][4];
#pragma unroll
                for (int s = 0; s < 2; s++)
#pragma unroll
                    for (int i = 0; i < 2; i++) {
                        uint32_t off = (uint32_t)((R0 + i * 16 + arow) * 64 +
                                                  (kk + acol) * 2);
                        LDSM4(af[s][i], base + s * ATILE + swz64(off));
                    }
#pragma unroll
                for (int j2 = 0; j2 < NFRAG / 2; j2++) {
                    uint32_t bfm[2][4];
#pragma unroll
                    for (int t = 0; t < 2; t++) {
                        uint32_t off = (uint32_t)((C0w + j2 * 16 + brow) * 64 +
                                                  (kk + bcol) * 2);
                        LDSM4(bfm[t], base + 2 * ATILE + t * WTILE + swz64(off));
                    }
                    constexpr int PS[3] = {1, 0, 0};
                    constexpr int PT[3] = {0, 1, 0};
#pragma unroll
                    for (int p = 0; p < 3; p++) {
                        const int s = PS[p], t = PT[p];
#pragma unroll
                        for (int i = 0; i < 2; i++) {
                            MMAF16(acc[i][2 * j2],     af[s][i],
                                   bfm[t][0], bfm[t][1]);
                            MMAF16(acc[i][2 * j2 + 1], af[s][i],
                                   bfm[t][2], bfm[t][3]);
                        }
                    }
                }
            }
            __syncthreads();
        }

        // ---- per-pass epilogue: bias, (fp32 store), stats ----
#pragma unroll
        for (int i = 0; i < 2; i++) {
            const int rla = R0 + i * 16 + (lane >> 2);
            float s1a = 0.f, s2a = 0.f, s1b = 0.f, s2b = 0.f;
#pragma unroll
            for (int j = 0; j < NFRAG; j++) {
                int cg = n0 + C0w + j * 8 + (lane & 3) * 2;
                acc[i][j][0] += bias_s[cg];
                acc[i][j][1] += bias_s[cg + 1];
                acc[i][j][2] += bias_s[cg];
                acc[i][j][3] += bias_s[cg + 1];
                if (OMODE == 0) {
                    *(float2*)(outf + (r0 + rla) * (int64_t)DOUT + cg) =
                        make_float2(acc[i][j][0], acc[i][j][1]);
                    *(float2*)(outf + (r0 + rla + 8) * (int64_t)DOUT + cg) =
                        make_float2(acc[i][j][2], acc[i][j][3]);
                }
                s1a += acc[i][j][0] + acc[i][j][1];
                s2a += fmaf(acc[i][j][0], acc[i][j][0],
                            acc[i][j][1] * acc[i][j][1]);
                s1b += acc[i][j][2] + acc[i][j][3];
                s2b += fmaf(acc[i][j][2], acc[i][j][2],
                            acc[i][j][3] * acc[i][j][3]);
            }
#pragma unroll
            for (int o = 1; o <= 2; o <<= 1) {
                s1a += __shfl_xor_sync(0xffffffffu, s1a, o);
                s2a += __shfl_xor_sync(0xffffffffu, s2a, o);
                s1b += __shfl_xor_sync(0xffffffffu, s1b, o);
                s2b += __shfl_xor_sync(0xffffffffu, s2b, o);
            }
            if ((lane & 3) == 0) {
                atomicAdd(&s1_s[rla], s1a);
                atomicAdd(&s2_s[rla], s2a);
                atomicAdd(&s1_s[rla + 8], s1b);
                atomicAdd(&s2_s[rla + 8], s2b);
            }
        }
    }

    __syncthreads();
    if (tid < TM) {
        float mu  = s1_s[tid] * (1.0f / DOUT);
        float var = s2_s[tid] * (1.0f / DOUT) - mu * mu;
        s1_s[tid] = mu;
        s2_s[tid] = rsqrtf(var + LN_EPS);
    }
    __syncthreads();

    if (OMODE == 0) {
        // phase-2: re-read own fp32 h tile (L2-hot), LN+ReLU+split -> planes
        const int row = tid >> 1;
        const int cb  = (tid & 1) * (DOUT / 2);
        const float mu = s1_s[row], rs = s2_s[row];
        const float* src = outf + (r0 + row) * (int64_t)DOUT + cb;
        const int64_t od = (r0 + row) * (int64_t)DOUT + cb;
#pragma unroll 2
        for (int c = 0; c < DOUT / 2; c += 8) {
            float4 v0 = *(const float4*)(src + c);
            float4 v1 = *(const float4*)(src + c + 4);
            float x[8] = {v0.x, v0.y, v0.z, v0.w, v1.x, v1.y, v1.z, v1.w};
            __half h0[8], h1[8];
#pragma unroll
            for (int j = 0; j < 8; j++) {
                int cc = cb + c + j;
                float y = fmaxf((x[j] - mu) * rs * go_s[cc] + bo_s[cc], 0.f);
                split2(y, h0[j], h1[j]);
            }
            *(uint4*)(o0 + od + c) =
                make_uint4(pack2(h0[0], h0[1]), pack2(h0[2], h0[3]),
                           pack2(h0[4], h0[5]), pack2(h0[6], h0[7]));
            *(uint4*)(o1 + od + c) =
                make_uint4(pack2(h1[0], h1[1]), pack2(h1[2], h1[3]),
                           pack2(h1[4], h1[5]), pack2(h1[6], h1[7]));
        }
    }

    if (OMODE == 1) {
        // LN3+ReLU+split from regs -> h3 limb tiles in (dead) buffer region
#pragma unroll
        for (int i = 0; i < 2; i++) {
            const int rla = R0 + i * 16 + (lane >> 2);
            float muA = s1_s[rla], rsA = s2_s[rla];
            float muB = s1_s[rla + 8], rsB = s2_s[rla + 8];
#pragma unroll
            for (int j = 0; j < NFRAG; j++) {
                int cg = C0w + j * 8 + (lane & 3) * 2;
                float ga = go_s[cg], gb = go_s[cg + 1];
                float ba = bo_s[cg], bb = bo_s[cg + 1];
                float v0 = fmaxf((acc[i][j][0] - muA) * rsA * ga + ba, 0.f);
                float v1 = fmaxf((acc[i][j][1] - muA) * rsA * gb + bb, 0.f);
                float v2 = fmaxf((acc[i][j][2] - muB) * rsB * ga + ba, 0.f);
                float v3 = fmaxf((acc[i][j][3] - muB) * rsB * gb + bb, 0.f);
                __half p0[2], p1[2], p2[2], p3[2];
                split2(v0, p0[0], p0[1]);
                split2(v1, p1[0], p1[1]);
                split2(v2, p2[0], p2[1]);
                split2(v3, p3[0], p3[1]);
                int kc = cg >> 5, kin = cg & 31;
                uint32_t oa = kc * 16384 + swz64((uint32_t)(rla * 64 + kin * 2));
                uint32_t ob = kc * 16384 +
                              swz64((uint32_t)((rla + 8) * 64 + kin * 2));
                *(uint32_t*)(sm + oa)        = pack2(p0[0], p1[0]);
                *(uint32_t*)(sm + oa + 8192) = pack2(p0[1], p1[1]);
                *(uint32_t*)(sm + ob)        = pack2(p2[0], p3[0]);
                *(uint32_t*)(sm + ob + 8192) = pack2(p2[1], p3[1]);
            }
        }
        __syncthreads();

        // ---- in-kernel L4: z[128x32] = h3[128x128] @ W4^T + b4 ----
        float a4[2][2][4];
#pragma unroll
        for (int i = 0; i < 2; i++)
#pragma unroll
            for (int jf = 0; jf < 2; jf++)
#pragma unroll
                for (int q = 0; q < 4; q++) a4[i][jf][q] = 0.f;
#pragma unroll
        for (int kc = 0; kc < 4; kc++)
#pragma unroll
            for (int kk = 0; kk < 32; kk += 16) {
                uint32_t af4[2][2][4];
#pragma unroll
                for (int s = 0; s < 2; s++)
#pragma unroll
                    for (int i = 0; i < 2; i++) {
                        uint32_t off = (uint32_t)((R0 + i * 16 + arow) * 64 +
                                                  (kk + acol) * 2);
                        LDSM4(af4[s][i],
                              smb + kc * 16384 + s * 8192 + swz64(off));
                    }
                uint32_t bf4[2][4];
#pragma unroll
                for (int t = 0; t < 2; t++) {
                    uint32_t off = (uint32_t)((wc * 16 + brow) * 64 +
                                              (kk + bcol) * 2);
                    LDSM4(bf4[t],
                          smb + W4OFF + (kc * 2 + t) * 2048 + swz64(off));
                }
                constexpr int PS[3] = {1, 0, 0};
                constexpr int PT[3] = {0, 1, 0};
#pragma unroll
                for (int p = 0; p < 3; p++) {
                    const int s = PS[p], t = PT[p];
#pragma unroll
                    for (int i = 0; i < 2; i++) {
                        MMAF16(a4[i][0], af4[s][i], bf4[t][0], bf4[t][1]);
                        MMAF16(a4[i][1], af4[s][i], bf4[t][2], bf4[t][3]);
                    }
                }
            }
#pragma unroll
        for (int i = 0; i < 2; i++) {
            const int rla = R0 + i * 16 + (lane >> 2);
#pragma unroll
            for (int jf = 0; jf < 2; jf++) {
                int c4 = wc * 16 + jf * 8 + (lane & 3) * 2;
                float bb0 = b4_s[c4], bb1 = b4_s[c4 + 1];
                *(float2*)(outf + (r0 + rla) * 32 + c4) =
                    make_float2(a4[i][jf][0] + bb0, a4[i][jf][1] + bb1);
                *(float2*)(outf + (r0 + rla + 8) * 32 + c4) =
                    make_float2(a4[i][jf][2] + bb0, a4[i][jf][3] + bb1);
            }
        }
    }
}

// ============================ prototypes ============================
__global__ void proto_accum_kernel(const int* __restrict__ labels,
                                   const float* __restrict__ zs) {
    __shared__ float ssum[64 * 32];
    __shared__ float scnt[64];
    int tid = threadIdx.x, lane = tid & 31, warp = tid >> 5;
    for (int t = tid; t < 64 * 32; t += 256) ssum[t] = 0.f;
    if (tid < 64) scnt[tid] = 0.f;
    __syncthreads();
    int rbase = blockIdx.x * 128;
    for (int r = rbase + warp; r < rbase + 128; r += 8) {
        int lab = labels[r];
        lab = max(0, min(63, lab));
        float v = zs[(size_t)r * 32 + lane];
        atomicAdd(&ssum[lab * 32 + lane], v);
        if (lane == 0) atomicAdd(&scnt[lab], 1.f);
    }
    __syncthreads();
    for (int t = tid; t < 64 * 32; t += 256) atomicAdd(&g_psum[t], ssum[t]);
    if (tid < 64) atomicAdd(&g_pcnt[tid], scnt[tid]);
}

__global__ void proto_finalize_kernel() {
    int tid = threadIdx.x;
    for (int i = tid; i < 64 * 32; i += 256) {
        int c = i >> 5;
        g_psum[i] = g_psum[i] / fmaxf(g_pcnt[c], 1.f);
    }
}

// ============================ -cdist ============================
__global__ __launch_bounds__(256) void dist_kernel(const float* __restrict__ zq,
                                                   float* __restrict__ out) {
    __shared__ float ps[64 * 33];
    __shared__ float pn[64];
    __shared__ float qs[16 * 33];
    int tid = threadIdx.x;
    for (int i = tid; i < 64 * 32; i += 256)
        ps[(i >> 5) * 33 + (i & 31)] = g_psum[i];
    int qbase = blockIdx.x * 16;
    for (int i = tid; i < 16 * 32; i += 256) {
        int q = i >> 5, k = i & 31;
        qs[q * 33 + k] = zq[(size_t)(qbase + q) * 32 + k];
    }
    __syncthreads();
    if (tid < 64) {
        float s = 0.f;
#pragma unroll
        for (int k = 0; k < 32; k++) {
            float v = ps[tid * 33 + k];
            s += v * v;
        }
        pn[tid] = s;
    }
    __syncthreads();
    int c = tid & 63;
#pragma unroll
    for (int p = 0; p < 4; p++) {
        int q = p * 4 + (tid >> 6);
        float dot = 0.f, qn = 0.f;
#pragma unroll
        for (int k = 0; k < 32; k++) {
            float a = qs[q * 33 + k];
            float b = ps[c * 33 + k];
            dot = fmaf(a, b, dot);
            qn  = fmaf(a, a, qn);
        }
        float sq = qn + pn[c] - 2.f * dot;
        out[(size_t)(qbase + q) * 64 + c] = -sqrtf(fmaxf(sq, 0.f));
    }
}

// ============================ launch ============================
extern "C" void kernel_launch(void* const* d_in, const int* in_sizes, int n_in,
                              void* d_out, int out_size) {
    const float* sup = (const float*)d_in[0];
    const int*   lab = (const int*)d_in[1];
    const float* qry = (const float*)d_in[2];
    const float* W1 = (const float*)d_in[3];
    const float* b1 = (const float*)d_in[4];
    const float* g1 = (const float*)d_in[5];
    const float* be1 = (const float*)d_in[6];
    const float* W2 = (const float*)d_in[7];
    const float* b2 = (const float*)d_in[8];
    const float* g2 = (const float*)d_in[9];
    const float* be2 = (const float*)d_in[10];
    const float* W3 = (const float*)d_in[11];
    const float* b3 = (const float*)d_in[12];
    const float* g3 = (const float*)d_in[13];
    const float* be3 = (const float*)d_in[14];
    const float* W4 = (const float*)d_in[15];
    const float* b4 = (const float*)d_in[16];

    cudaFuncSetAttribute(layer_kernel<768, 512, 0>,
                         cudaFuncAttributeMaxDynamicSharedMemorySize,
                         smem_of(512, 0));
    cudaFuncSetAttribute(layer_kernel<512, 512, 0>,
                         cudaFuncAttributeMaxDynamicSharedMemorySize,
                         smem_of(512, 0));
    cudaFuncSetAttribute(layer_kernel<512, 128, 1>,
                         cudaFuncAttributeMaxDynamicSharedMemorySize,
                         smem_of(128, 1));

    float* h = nullptr;
    __half *a0, *a1, *c0, *c1;
    cudaGetSymbolAddress((void**)&h, g_h);
    cudaGetSymbolAddress((void**)&a0, g_a0);
    cudaGetSymbolAddress((void**)&a1, g_a1);
    cudaGetSymbolAddress((void**)&c0, g_c0);
    cudaGetSymbolAddress((void**)&c1, g_c1);

    // 1: weight split + proto zeroing
    split_w_all<<<(724992 + 255) / 256, 256>>>(W1, W2, W3, W4);
    // 2-3: input converts
    convert_in<<<12288, 256>>>(sup, a0, a1, 32768 * 96);
    convert_in<<<24576, 256>>>(qry, a0 + (int64_t)32768 * 768,
                               a1 + (int64_t)32768 * 768, 65536 * 96);
    // 4: L1 -> h + planes c (LN1+ReLU fused)   [profiled slot]
    layer_kernel<768, 512, 0><<<768, 256, smem_of(512, 0)>>>(
        a0, a1, 0, b1, g1, be1, nullptr, h, c0, c1);
    // 5: L2 -> h + planes a (LN2+ReLU fused)
    layer_kernel<512, 512, 0><<<768, 256, smem_of(512, 0)>>>(
        c0, c1, 393216, b2, g2, be2, nullptr, h, a0, a1);
    // 6: L3 (planes a) + fused LN3/ReLU + in-kernel L4 -> z in h
    layer_kernel<512, 128, 1><<<768, 256, smem_of(128, 1)>>>(
        a0, a1, 655360, b3, g3, be3, b4, h, nullptr, nullptr);
    // 7+: prototypes + distances
    proto_accum_kernel<<<256, 256>>>(lab, h);
    proto_finalize_kernel<<<1, 256>>>();
    dist_kernel<<<65536 / 16, 256>>>(h + (size_t)32768 * 32, (float*)d_out);
}